// round 16
// baseline (speedup 1.0000x reference)
#include <cuda_runtime.h>
#include <cuda_bf16.h>
#include <cstdint>

// Problem constants (fixed by the dataset)
#define NN 100000
#define NE 1600000
#define NG 64
#define C_IN 128
#define C_HID 128
#define C_OUT 64
#define N_CLS 2

// ---------------- scratch (device globals: no allocation allowed) ----------
__device__ uint32_t g_H[NN * 64];      // GEMM output h = X @ W, bf16x2 packed
__device__ uint32_t g_X[NN * 64];      // layer activations, bf16x2 packed
__device__ float g_dinv[NN];           // 1/sqrt(deg), deg = 1 + indeg
__device__ int   g_cnt[NN];            // in-degree histogram
__device__ int   g_rowoff[NN + 1];     // CSR offsets (dst-sorted)
__device__ int   g_cursor[NN];         // counting-sort cursors
__device__ int2  g_edge[NE];           // (src, weight-bits) sorted by dst
__device__ float g_pool[NG * C_OUT];   // per-graph sums
__device__ float g_gcnt[NG];           // per-graph node counts
__device__ int   g_bsums[128];         // scan block sums

// W packed as bf16 hi/lo in m16n8k16 B-fragment order (u32 granules)
__device__ uint32_t g_W1h[8192], g_W1l[8192];
__device__ uint32_t g_W2h[8192], g_W2l[8192];
__device__ uint32_t g_W3h[4096], g_W3l[4096];

// ---------------- preprocessing kernels ------------------------------------
// fused: zero counters/pool + pack W (fp32 [K][N]) into hi/lo bf16 fragments
__global__ void k_pre(const float* __restrict__ W1, const float* __restrict__ W2,
                      const float* __restrict__ W3) {
    int i = blockIdx.x * blockDim.x + threadIdx.x;
    if (i < NN) g_cnt[i] = 0;
    if (i < NG * C_OUT) g_pool[i] = 0.f;
    if (i < NG) g_gcnt[i] = 0.f;
    if (i >= 2 * 128 * 128 + 128 * 64) return;
    const float* W;
    uint32_t *Wh, *Wl;
    int e, Nout;
    if (i < 16384)      { W = W1; Wh = g_W1h; Wl = g_W1l; e = i;          Nout = 128; }
    else if (i < 32768) { W = W2; Wh = g_W2h; Wl = g_W2l; e = i - 16384;  Nout = 128; }
    else                { W = W3; Wh = g_W3h; Wl = g_W3l; e = i - 32768;  Nout = 64; }
    int k = e / Nout, n = e % Nout;
    float v = W[e];
    __nv_bfloat16 bh = __float2bfloat16_rn(v);
    __nv_bfloat16 bl = __float2bfloat16_rn(v - __bfloat162float(bh));
    int j = n >> 3, g = n & 7, s = k >> 4, kk = k & 15;
    int tg = (kk >> 1) & 3, r = kk >> 3, h = kk & 1, lane = g * 4 + tg;
    int u = ((j * 8 + s) * 32 + lane) * 2 + r;
    ((uint16_t*)Wh)[u * 2 + h] = __bfloat16_as_ushort(bh);
    ((uint16_t*)Wl)[u * 2 + h] = __bfloat16_as_ushort(bl);
}

// degree histogram, int4-vectorized loads (NE % 4 == 0, dst is 16B-aligned)
__global__ void k_hist(const int4* __restrict__ dst4) {
    int e = blockIdx.x * blockDim.x + threadIdx.x;
    if (e >= NE / 4) return;
    int4 d = dst4[e];
    atomicAdd(&g_cnt[d.x], 1);
    atomicAdd(&g_cnt[d.y], 1);
    atomicAdd(&g_cnt[d.z], 1);
    atomicAdd(&g_cnt[d.w], 1);
}

// scan over g_cnt -> g_rowoff (exclusive). 1024 items per block.
__global__ void k_scan1() {
    __shared__ int sm[256];
    int tid = threadIdx.x;
    int base = blockIdx.x * 1024;
    int v[4];
    int ts = 0;
#pragma unroll
    for (int u = 0; u < 4; u++) {
        int idx = base + tid * 4 + u;
        v[u] = (idx < NN) ? g_cnt[idx] : 0;
        ts += v[u];
    }
    sm[tid] = ts;
    __syncthreads();
    for (int off = 1; off < 256; off <<= 1) {
        int x = (tid >= off) ? sm[tid - off] : 0;
        __syncthreads();
        sm[tid] += x;
        __syncthreads();
    }
    int run = sm[tid] - ts;
#pragma unroll
    for (int u = 0; u < 4; u++) {
        int idx = base + tid * 4 + u;
        if (idx < NN) g_rowoff[idx] = run;
        run += v[u];
    }
    if (tid == 255) g_bsums[blockIdx.x] = sm[255];
}

__global__ void k_scan2(int nb) {
    __shared__ int sm[128];
    int tid = threadIdx.x;
    if (tid < nb) sm[tid] = g_bsums[tid];
    __syncthreads();
    if (tid == 0) {
        int acc = 0;
        for (int i = 0; i < nb; i++) { int t = sm[i]; sm[i] = acc; acc += t; }
        g_rowoff[NN] = acc;
    }
    __syncthreads();
    if (tid < nb) g_bsums[tid] = sm[tid];
}

// scan fixup + cursor init + dinv (fused: all are per-node elementwise)
__global__ void k_scan3() {
    int i = blockIdx.x * blockDim.x + threadIdx.x;
    if (i < NN) {
        int v = g_rowoff[i] + g_bsums[i >> 10];
        g_rowoff[i] = v;
        g_cursor[i] = v;
        g_dinv[i] = rsqrtf(1.0f + (float)g_cnt[i]);
    }
}

__global__ void k_esort(const int* __restrict__ src, const int* __restrict__ dst) {
    int e = blockIdx.x * blockDim.x + threadIdx.x;
    if (e >= NE) return;
    int s = src[e], d = dst[e];
    int p = atomicAdd(&g_cursor[d], 1);
    g_edge[p] = make_int2(s, __float_as_int(g_dinv[s] * g_dinv[d]));
}

// ---------------- HMMA GEMM: H[n, NOUT] = X[n, 128] @ W[128, NOUT] ---------
// X rounded to bf16 (Xh); W kept split bf16 hi/lo: D = Xh*Wh + Xh*Wl.
// W fragments read straight from global (L2-resident, shared by all blocks);
// smem holds only the Xh tile (34.8 KB) -> 2 CTAs/SM.
__device__ __forceinline__ void mma_bf16(float* c, const uint32_t* a,
                                         uint32_t b0, uint32_t b1) {
    asm volatile(
        "mma.sync.aligned.m16n8k16.row.col.f32.bf16.bf16.f32 "
        "{%0,%1,%2,%3}, {%4,%5,%6,%7}, {%8,%9}, {%0,%1,%2,%3};"
        : "+f"(c[0]), "+f"(c[1]), "+f"(c[2]), "+f"(c[3])
        : "r"(a[0]), "r"(a[1]), "r"(a[2]), "r"(a[3]), "r"(b0), "r"(b1));
}

__device__ __forceinline__ uint32_t pack_bf16x2(float a, float b) {
    __nv_bfloat162 p = __float22bfloat162_rn(make_float2(a, b));
    return *reinterpret_cast<uint32_t*>(&p);
}

// X smem: padded row stride 68 u32 (136 halves) -> conflict-free frag loads.
#define XSTRIDE 68
#define XWORDS (128 * XSTRIDE)   // 8704 u32

// BF16IN=false: X fp32 [n,128]; BF16IN=true: X bf16x2 packed [n,64] (u32)
template <int NOUT, bool BF16IN>
__global__ __launch_bounds__(256, 2) void k_mmagemm(const void* __restrict__ Xin,
                                                    const uint32_t* __restrict__ Wfh,
                                                    const uint32_t* __restrict__ Wfl,
                                                    uint32_t* __restrict__ H, int n) {
    extern __shared__ uint32_t smem[];
    uint32_t* Xh = smem;

    const int tid = threadIdx.x;
    const int wid = tid >> 5;
    const int lane = tid & 31;
    const int base = blockIdx.x * 128;

    // ---- stage X tile as bf16 into smem ----
    if (BF16IN) {
        const uint4* Xb = (const uint4*)Xin;   // 16 uint4 per row
#pragma unroll 4
        for (int it = 0; it < 8; it++) {
            int chunk = it * 256 + tid;        // 2048 uint4 chunks
            int row = chunk >> 4;
            int q = chunk & 15;
            int grow = base + row;
            uint4 v = make_uint4(0u, 0u, 0u, 0u);
            if (grow < n) v = __ldcs(&Xb[(size_t)grow * 16 + q]);
            int o = row * XSTRIDE + q * 4;
            Xh[o] = v.x; Xh[o + 1] = v.y; Xh[o + 2] = v.z; Xh[o + 3] = v.w;
        }
    } else {
        const float4* Xf = (const float4*)Xin;
#pragma unroll 4
        for (int it = 0; it < 16; it++) {
            int chunk = it * 256 + tid;        // 4096 float4 chunks
            int row = chunk >> 5;
            int c4 = chunk & 31;
            int grow = base + row;
            float4 v = make_float4(0.f, 0.f, 0.f, 0.f);
            if (grow < n) v = __ldcs(&Xf[(size_t)grow * 32 + c4]);
            int o = row * XSTRIDE + c4 * 2;
            Xh[o] = pack_bf16x2(v.x, v.y);
            Xh[o + 1] = pack_bf16x2(v.z, v.w);
        }
    }
    __syncthreads();

    // warp tiling: NOUT=128 -> 4x2 warps, 32 rows x 64 cols each (MT=2).
    //              NOUT=64  -> 8x1 warps, 16 rows x 64 cols each (MT=1).
    constexpr int MT = (NOUT == 128) ? 2 : 1;
    const int wm = (NOUT == 128) ? (wid >> 1) * 2 : wid;  // first m-tile (16-row units)
    const int ncol0 = (NOUT == 128) ? (wid & 1) * 8 : 0;  // first n-tile (8-col units)
    const int g = lane >> 2;
    const int tg = lane & 3;

    float acc[MT][8][4];
#pragma unroll
    for (int mt = 0; mt < MT; mt++)
#pragma unroll
        for (int j = 0; j < 8; j++)
#pragma unroll
            for (int q = 0; q < 4; q++) acc[mt][j][q] = 0.f;

#pragma unroll
    for (int s = 0; s < 8; s++) {
        uint32_t ah[MT][4];
#pragma unroll
        for (int mt = 0; mt < MT; mt++) {
            int r0 = (wm + mt) * 16 + g;
            int p0 = s * 8 + tg;
            ah[mt][0] = Xh[r0 * XSTRIDE + p0];
            ah[mt][1] = Xh[(r0 + 8) * XSTRIDE + p0];
            ah[mt][2] = Xh[r0 * XSTRIDE + p0 + 4];
            ah[mt][3] = Xh[(r0 + 8) * XSTRIDE + p0 + 4];
        }
#pragma unroll
        for (int j = 0; j < 8; j++) {
            int widx = ((ncol0 + j) * 8 + s) * 32 + lane;   // uint2 index
            uint2 bh = __ldg((const uint2*)Wfh + widx);
            uint2 bl = __ldg((const uint2*)Wfl + widx);
#pragma unroll
            for (int mt = 0; mt < MT; mt++) {
                mma_bf16(acc[mt][j], ah[mt], bh.x, bh.y);
                mma_bf16(acc[mt][j], ah[mt], bl.x, bl.y);
            }
        }
    }

    // ---- epilogue: fragment -> bf16x2 packed H ----
#pragma unroll
    for (int mt = 0; mt < MT; mt++) {
#pragma unroll
        for (int j = 0; j < 8; j++) {
            int row = base + (wm + mt) * 16 + g;
            int col = (ncol0 + j) * 8 + tg * 2;      // even column
            if (row < n)
                H[(size_t)row * (NOUT / 2) + col / 2] = pack_bf16x2(acc[mt][j][0], acc[mt][j][1]);
            if (row + 8 < n)
                H[(size_t)(row + 8) * (NOUT / 2) + col / 2] = pack_bf16x2(acc[mt][j][2], acc[mt][j][3]);
        }
    }
}

// ---------------- aggregation: warp-per-node gather over sorted CSR --------
// H is bf16x2 packed. 2-edge software pipeline, single accumulator.
// Edge loads use DEFAULT caching: one 128B edge line serves 16 consecutive
// edges of the same warp (L1-resident reuse) — do NOT stream these.
template <int C, bool RELU, bool POOL>
__global__ __launch_bounds__(256) void k_agg(const uint32_t* __restrict__ H,
                                             const float* __restrict__ bias,
                                             uint32_t* __restrict__ Xo,
                                             const int* __restrict__ batch,
                                             int n) {
    int w = (blockIdx.x * blockDim.x + threadIdx.x) >> 5;
    int lane = threadIdx.x & 31;
    if (w >= n) return;
    int beg = g_rowoff[w];
    int end = g_rowoff[w + 1];

    if (C == 128) {
        float4 acc = make_float4(0.f, 0.f, 0.f, 0.f);
        const uint2* H2 = (const uint2*)H;   // 32 uint2 per row
        int j = beg;
        for (; j + 1 < end; j += 2) {
            int2 e0 = __ldg(&g_edge[j]);
            int2 e1 = __ldg(&g_edge[j + 1]);
            uint2 v0 = H2[(size_t)e0.x * 32 + lane];
            uint2 v1 = H2[(size_t)e1.x * 32 + lane];
            float wt0 = __int_as_float(e0.y);
            float wt1 = __int_as_float(e1.y);
            float2 a0 = __bfloat1622float2(*reinterpret_cast<__nv_bfloat162*>(&v0.x));
            float2 a1 = __bfloat1622float2(*reinterpret_cast<__nv_bfloat162*>(&v0.y));
            float2 b0 = __bfloat1622float2(*reinterpret_cast<__nv_bfloat162*>(&v1.x));
            float2 b1 = __bfloat1622float2(*reinterpret_cast<__nv_bfloat162*>(&v1.y));
            acc.x = fmaf(wt0, a0.x, acc.x);
            acc.y = fmaf(wt0, a0.y, acc.y);
            acc.z = fmaf(wt0, a1.x, acc.z);
            acc.w = fmaf(wt0, a1.y, acc.w);
            acc.x = fmaf(wt1, b0.x, acc.x);
            acc.y = fmaf(wt1, b0.y, acc.y);
            acc.z = fmaf(wt1, b1.x, acc.z);
            acc.w = fmaf(wt1, b1.y, acc.w);
        }
        if (j < end) {
            int2 e = __ldg(&g_edge[j]);
            float wt = __int_as_float(e.y);
            uint2 v = H2[(size_t)e.x * 32 + lane];
            float2 f0 = __bfloat1622float2(*reinterpret_cast<__nv_bfloat162*>(&v.x));
            float2 f1 = __bfloat1622float2(*reinterpret_cast<__nv_bfloat162*>(&v.y));
            acc.x = fmaf(wt, f0.x, acc.x);
            acc.y = fmaf(wt, f0.y, acc.y);
            acc.z = fmaf(wt, f1.x, acc.z);
            acc.w = fmaf(wt, f1.y, acc.w);
        }
        float di = g_dinv[w];
        float sl = di * di;
        uint2 v = H2[(size_t)w * 32 + lane];
        float2 h0 = __bfloat1622float2(*reinterpret_cast<__nv_bfloat162*>(&v.x));
        float2 h1 = __bfloat1622float2(*reinterpret_cast<__nv_bfloat162*>(&v.y));
        float4 bb = *(const float4*)&bias[lane * 4];
        acc.x = fmaf(sl, h0.x, acc.x) + bb.x;
        acc.y = fmaf(sl, h0.y, acc.y) + bb.y;
        acc.z = fmaf(sl, h1.x, acc.z) + bb.z;
        acc.w = fmaf(sl, h1.y, acc.w) + bb.w;
        if (RELU) {
            acc.x = fmaxf(acc.x, 0.f); acc.y = fmaxf(acc.y, 0.f);
            acc.z = fmaxf(acc.z, 0.f); acc.w = fmaxf(acc.w, 0.f);
        }
        // write as bf16x2 packed, streaming (consumed once by next GEMM)
        uint2 o;
        o.x = pack_bf16x2(acc.x, acc.y);
        o.y = pack_bf16x2(acc.z, acc.w);
        __stcs((uint2*)&Xo[(size_t)w * 64 + lane * 2], o);
    } else {  // C == 64
        float2 acc = make_float2(0.f, 0.f);
        int j = beg;
        for (; j + 1 < end; j += 2) {
            int2 e0 = __ldg(&g_edge[j]);
            int2 e1 = __ldg(&g_edge[j + 1]);
            uint32_t v0 = H[(size_t)e0.x * 32 + lane];
            uint32_t v1 = H[(size_t)e1.x * 32 + lane];
            float wt0 = __int_as_float(e0.y);
            float wt1 = __int_as_float(e1.y);
            float2 f0 = __bfloat1622float2(*reinterpret_cast<__nv_bfloat162*>(&v0));
            float2 f1 = __bfloat1622float2(*reinterpret_cast<__nv_bfloat162*>(&v1));
            acc.x = fmaf(wt0, f0.x, acc.x);
            acc.y = fmaf(wt0, f0.y, acc.y);
            acc.x = fmaf(wt1, f1.x, acc.x);
            acc.y = fmaf(wt1, f1.y, acc.y);
        }
        if (j < end) {
            int2 e = __ldg(&g_edge[j]);
            float wt = __int_as_float(e.y);
            uint32_t v = H[(size_t)e.x * 32 + lane];
            float2 f = __bfloat1622float2(*reinterpret_cast<__nv_bfloat162*>(&v));
            acc.x = fmaf(wt, f.x, acc.x);
            acc.y = fmaf(wt, f.y, acc.y);
        }
        float di = g_dinv[w];
        float sl = di * di;
        uint32_t v = H[(size_t)w * 32 + lane];
        float2 hd = __bfloat1622float2(*reinterpret_cast<__nv_bfloat162*>(&v));
        float2 bb = *(const float2*)&bias[lane * 2];
        acc.x = fmaf(sl, hd.x, acc.x) + bb.x;
        acc.y = fmaf(sl, hd.y, acc.y) + bb.y;
        if (RELU) { acc.x = fmaxf(acc.x, 0.f); acc.y = fmaxf(acc.y, 0.f); }
        if (POOL) {
            int b = batch[w];
            atomicAdd(&g_pool[b * C_OUT + lane * 2 + 0], acc.x);
            atomicAdd(&g_pool[b * C_OUT + lane * 2 + 1], acc.y);
            if (lane == 0) atomicAdd(&g_gcnt[b], 1.0f);
        }
    }
}

// ---------------- final FC on pooled means ----------------------------------
__global__ void k_fc(const float* __restrict__ Wfc, const float* __restrict__ bfc,
                     float* __restrict__ out) {
    int t = threadIdx.x;  // 128 = 64 graphs * 2 classes
    int g = t >> 1, c = t & 1;
    float s = 0.f;
#pragma unroll
    for (int k = 0; k < C_OUT; k++) s = fmaf(g_pool[g * C_OUT + k], Wfc[k * N_CLS + c], s);
    out[g * N_CLS + c] = s / fmaxf(g_gcnt[g], 1.0f) + bfc[c];
}

// ---------------- launch ----------------------------------------------------
extern "C" void kernel_launch(void* const* d_in, const int* in_sizes, int n_in,
                              void* d_out, int out_size) {
    const float* x    = (const float*)d_in[0];
    const int*   ei   = (const int*)d_in[1];
    const int*   batch= (const int*)d_in[2];
    const float* W1   = (const float*)d_in[3];
    const float* b1   = (const float*)d_in[4];
    const float* W2   = (const float*)d_in[5];
    const float* b2   = (const float*)d_in[6];
    const float* W3   = (const float*)d_in[7];
    const float* b3   = (const float*)d_in[8];
    const float* Wfc  = (const float*)d_in[9];
    const float* bfc  = (const float*)d_in[10];
    float* out = (float*)d_out;

    const int* src = ei;
    const int* dst = ei + NE;

    void *pH, *pX, *p1h, *p1l, *p2h, *p2l, *p3h, *p3l;
    cudaGetSymbolAddress(&pH, g_H);
    cudaGetSymbolAddress(&pX, g_X);
    cudaGetSymbolAddress(&p1h, g_W1h);
    cudaGetSymbolAddress(&p1l, g_W1l);
    cudaGetSymbolAddress(&p2h, g_W2h);
    cudaGetSymbolAddress(&p2l, g_W2l);
    cudaGetSymbolAddress(&p3h, g_W3h);
    cudaGetSymbolAddress(&p3l, g_W3l);
    uint32_t* H = (uint32_t*)pH;
    uint32_t* X = (uint32_t*)pX;

    const int SMEM = XWORDS * 4;   // 34816 B (Xh tile only)
    cudaFuncSetAttribute((void*)k_mmagemm<128, false>, cudaFuncAttributeMaxDynamicSharedMemorySize, SMEM);
    cudaFuncSetAttribute((void*)k_mmagemm<128, true>,  cudaFuncAttributeMaxDynamicSharedMemorySize, SMEM);
    cudaFuncSetAttribute((void*)k_mmagemm<64, true>,   cudaFuncAttributeMaxDynamicSharedMemorySize, SMEM);

    const int NB = (NN + 1023) / 1024;  // 98 scan blocks
    const int gemm_grid = (NN + 127) / 128;  // 782
    const int agg_grid  = (NN + 7) / 8;      // 8 warps/block, warp per node

    // preprocessing + layer-1 GEMM placed so the profiler window catches it
    k_pre<<<(NN + 255) / 256, 256>>>(W1, W2, W3);     // zero + W pack (fused)
    k_hist<<<(NE / 4 + 255) / 256, 256>>>((const int4*)dst);
    k_mmagemm<128, false><<<gemm_grid, 256, SMEM>>>(x, (const uint32_t*)p1h,
                                                    (const uint32_t*)p1l, H, NN);
    k_scan1<<<NB, 256>>>();
    k_scan2<<<1, 128>>>(NB);
    k_scan3<<<(NN + 255) / 256, 256>>>();   // fused: fixup + cursor + dinv
    k_esort<<<(NE + 255) / 256, 256>>>(src, dst);

    // layer 1 agg
    k_agg<128, true, false><<<agg_grid, 256>>>(H, b1, X, nullptr, NN);
    // layer 2
    k_mmagemm<128, true><<<gemm_grid, 256, SMEM>>>(X, (const uint32_t*)p2h,
                                                   (const uint32_t*)p2l, H, NN);
    k_agg<128, true, false><<<agg_grid, 256>>>(H, b2, X, nullptr, NN);
    // layer 3 (C=64), pooling fused
    k_mmagemm<64, true><<<gemm_grid, 256, SMEM>>>(X, (const uint32_t*)p3h,
                                                  (const uint32_t*)p3l, H, NN);
    k_agg<64, false, true><<<agg_grid, 256>>>(H, b3, nullptr, batch, NN);
    // FC head
    k_fc<<<1, 128>>>(Wfc, bfc, out);
}

// round 17
// speedup vs baseline: 1.0164x; 1.0164x over previous
#include <cuda_runtime.h>
#include <cuda_bf16.h>
#include <cstdint>

// Problem constants (fixed by the dataset)
#define NN 100000
#define NE 1600000
#define NG 64
#define C_IN 128
#define C_HID 128
#define C_OUT 64
#define N_CLS 2

// ---------------- scratch (device globals: no allocation allowed) ----------
__device__ uint32_t g_H[NN * 64];      // GEMM output h = X @ W, bf16x2 packed
__device__ uint32_t g_X[NN * 64];      // layer activations, bf16x2 packed
__device__ float g_dinv[NN];           // 1/sqrt(deg), deg = 1 + indeg
__device__ int   g_cnt[NN];            // in-degree histogram
__device__ int   g_rowoff[NN + 1];     // CSR offsets (dst-sorted)
__device__ int   g_cursor[NN];         // counting-sort cursors
__device__ int2  g_edge[NE];           // (src, weight-bits) sorted by dst
__device__ float g_pool[NG * C_OUT];   // per-graph sums
__device__ float g_gcnt[NG];           // per-graph node counts
__device__ int   g_bsums[128];         // scan block sums

// W packed as bf16 hi/lo in m16n8k16 B-fragment order (u32 granules)
__device__ uint32_t g_W1h[8192], g_W1l[8192];
__device__ uint32_t g_W2h[8192], g_W2l[8192];
__device__ uint32_t g_W3h[4096], g_W3l[4096];

// ---------------- preprocessing kernels ------------------------------------
// fused: zero counters/pool + pack W (fp32 [K][N]) into hi/lo bf16 fragments
__global__ void k_pre(const float* __restrict__ W1, const float* __restrict__ W2,
                      const float* __restrict__ W3) {
    int i = blockIdx.x * blockDim.x + threadIdx.x;
    if (i < NN) g_cnt[i] = 0;
    if (i < NG * C_OUT) g_pool[i] = 0.f;
    if (i < NG) g_gcnt[i] = 0.f;
    if (i >= 2 * 128 * 128 + 128 * 64) return;
    const float* W;
    uint32_t *Wh, *Wl;
    int e, Nout;
    if (i < 16384)      { W = W1; Wh = g_W1h; Wl = g_W1l; e = i;          Nout = 128; }
    else if (i < 32768) { W = W2; Wh = g_W2h; Wl = g_W2l; e = i - 16384;  Nout = 128; }
    else                { W = W3; Wh = g_W3h; Wl = g_W3l; e = i - 32768;  Nout = 64; }
    int k = e / Nout, n = e % Nout;
    float v = W[e];
    __nv_bfloat16 bh = __float2bfloat16_rn(v);
    __nv_bfloat16 bl = __float2bfloat16_rn(v - __bfloat162float(bh));
    int j = n >> 3, g = n & 7, s = k >> 4, kk = k & 15;
    int tg = (kk >> 1) & 3, r = kk >> 3, h = kk & 1, lane = g * 4 + tg;
    int u = ((j * 8 + s) * 32 + lane) * 2 + r;
    ((uint16_t*)Wh)[u * 2 + h] = __bfloat16_as_ushort(bh);
    ((uint16_t*)Wl)[u * 2 + h] = __bfloat16_as_ushort(bl);
}

// degree histogram, int4-vectorized loads (NE % 4 == 0, dst is 16B-aligned)
__global__ void k_hist(const int4* __restrict__ dst4) {
    int e = blockIdx.x * blockDim.x + threadIdx.x;
    if (e >= NE / 4) return;
    int4 d = dst4[e];
    atomicAdd(&g_cnt[d.x], 1);
    atomicAdd(&g_cnt[d.y], 1);
    atomicAdd(&g_cnt[d.z], 1);
    atomicAdd(&g_cnt[d.w], 1);
}

// scan over g_cnt -> g_rowoff (exclusive). 1024 items per block.
__global__ void k_scan1() {
    __shared__ int sm[256];
    int tid = threadIdx.x;
    int base = blockIdx.x * 1024;
    int v[4];
    int ts = 0;
#pragma unroll
    for (int u = 0; u < 4; u++) {
        int idx = base + tid * 4 + u;
        v[u] = (idx < NN) ? g_cnt[idx] : 0;
        ts += v[u];
    }
    sm[tid] = ts;
    __syncthreads();
    for (int off = 1; off < 256; off <<= 1) {
        int x = (tid >= off) ? sm[tid - off] : 0;
        __syncthreads();
        sm[tid] += x;
        __syncthreads();
    }
    int run = sm[tid] - ts;
#pragma unroll
    for (int u = 0; u < 4; u++) {
        int idx = base + tid * 4 + u;
        if (idx < NN) g_rowoff[idx] = run;
        run += v[u];
    }
    if (tid == 255) g_bsums[blockIdx.x] = sm[255];
}

__global__ void k_scan2(int nb) {
    __shared__ int sm[128];
    int tid = threadIdx.x;
    if (tid < nb) sm[tid] = g_bsums[tid];
    __syncthreads();
    if (tid == 0) {
        int acc = 0;
        for (int i = 0; i < nb; i++) { int t = sm[i]; sm[i] = acc; acc += t; }
        g_rowoff[NN] = acc;
    }
    __syncthreads();
    if (tid < nb) g_bsums[tid] = sm[tid];
}

// scan fixup + cursor init + dinv (fused: all are per-node elementwise)
__global__ void k_scan3() {
    int i = blockIdx.x * blockDim.x + threadIdx.x;
    if (i < NN) {
        int v = g_rowoff[i] + g_bsums[i >> 10];
        g_rowoff[i] = v;
        g_cursor[i] = v;
        g_dinv[i] = rsqrtf(1.0f + (float)g_cnt[i]);
    }
}

__global__ void k_esort(const int* __restrict__ src, const int* __restrict__ dst) {
    int e = blockIdx.x * blockDim.x + threadIdx.x;
    if (e >= NE) return;
    int s = src[e], d = dst[e];
    int p = atomicAdd(&g_cursor[d], 1);
    g_edge[p] = make_int2(s, __float_as_int(g_dinv[s] * g_dinv[d]));
}

// ---------------- HMMA GEMM: H[n, NOUT] = X[n, 128] @ W[128, NOUT] ---------
// X rounded to bf16 (Xh); W kept split bf16 hi/lo: D = Xh*Wh + Xh*Wl.
// W fragments read straight from global (L2-resident, shared by all blocks);
// smem holds only the Xh tile (34.8 KB) -> 2 CTAs/SM.
__device__ __forceinline__ void mma_bf16(float* c, const uint32_t* a,
                                         uint32_t b0, uint32_t b1) {
    asm volatile(
        "mma.sync.aligned.m16n8k16.row.col.f32.bf16.bf16.f32 "
        "{%0,%1,%2,%3}, {%4,%5,%6,%7}, {%8,%9}, {%0,%1,%2,%3};"
        : "+f"(c[0]), "+f"(c[1]), "+f"(c[2]), "+f"(c[3])
        : "r"(a[0]), "r"(a[1]), "r"(a[2]), "r"(a[3]), "r"(b0), "r"(b1));
}

__device__ __forceinline__ uint32_t pack_bf16x2(float a, float b) {
    __nv_bfloat162 p = __float22bfloat162_rn(make_float2(a, b));
    return *reinterpret_cast<uint32_t*>(&p);
}

// X smem: padded row stride 68 u32 (136 halves) -> conflict-free frag loads.
#define XSTRIDE 68
#define XWORDS (128 * XSTRIDE)   // 8704 u32

// BF16IN=false: X fp32 [n,128]; BF16IN=true: X bf16x2 packed [n,64] (u32)
template <int NOUT, bool BF16IN>
__global__ __launch_bounds__(256, 2) void k_mmagemm(const void* __restrict__ Xin,
                                                    const uint32_t* __restrict__ Wfh,
                                                    const uint32_t* __restrict__ Wfl,
                                                    uint32_t* __restrict__ H, int n) {
    extern __shared__ uint32_t smem[];
    uint32_t* Xh = smem;

    const int tid = threadIdx.x;
    const int wid = tid >> 5;
    const int lane = tid & 31;
    const int base = blockIdx.x * 128;

    // ---- stage X tile as bf16 into smem ----
    if (BF16IN) {
        const uint4* Xb = (const uint4*)Xin;   // 16 uint4 per row
#pragma unroll 4
        for (int it = 0; it < 8; it++) {
            int chunk = it * 256 + tid;        // 2048 uint4 chunks
            int row = chunk >> 4;
            int q = chunk & 15;
            int grow = base + row;
            uint4 v = make_uint4(0u, 0u, 0u, 0u);
            if (grow < n) v = __ldcs(&Xb[(size_t)grow * 16 + q]);
            int o = row * XSTRIDE + q * 4;
            Xh[o] = v.x; Xh[o + 1] = v.y; Xh[o + 2] = v.z; Xh[o + 3] = v.w;
        }
    } else {
        const float4* Xf = (const float4*)Xin;
#pragma unroll 4
        for (int it = 0; it < 16; it++) {
            int chunk = it * 256 + tid;        // 4096 float4 chunks
            int row = chunk >> 5;
            int c4 = chunk & 31;
            int grow = base + row;
            float4 v = make_float4(0.f, 0.f, 0.f, 0.f);
            if (grow < n) v = __ldcs(&Xf[(size_t)grow * 32 + c4]);
            int o = row * XSTRIDE + c4 * 2;
            Xh[o] = pack_bf16x2(v.x, v.y);
            Xh[o + 1] = pack_bf16x2(v.z, v.w);
        }
    }
    __syncthreads();

    // warp tiling: NOUT=128 -> 4x2 warps, 32 rows x 64 cols each (MT=2).
    //              NOUT=64  -> 8x1 warps, 16 rows x 64 cols each (MT=1).
    constexpr int MT = (NOUT == 128) ? 2 : 1;
    const int wm = (NOUT == 128) ? (wid >> 1) * 2 : wid;  // first m-tile (16-row units)
    const int ncol0 = (NOUT == 128) ? (wid & 1) * 8 : 0;  // first n-tile (8-col units)
    const int g = lane >> 2;
    const int tg = lane & 3;

    float acc[MT][8][4];
#pragma unroll
    for (int mt = 0; mt < MT; mt++)
#pragma unroll
        for (int j = 0; j < 8; j++)
#pragma unroll
            for (int q = 0; q < 4; q++) acc[mt][j][q] = 0.f;

#pragma unroll
    for (int s = 0; s < 8; s++) {
        uint32_t ah[MT][4];
#pragma unroll
        for (int mt = 0; mt < MT; mt++) {
            int r0 = (wm + mt) * 16 + g;
            int p0 = s * 8 + tg;
            ah[mt][0] = Xh[r0 * XSTRIDE + p0];
            ah[mt][1] = Xh[(r0 + 8) * XSTRIDE + p0];
            ah[mt][2] = Xh[r0 * XSTRIDE + p0 + 4];
            ah[mt][3] = Xh[(r0 + 8) * XSTRIDE + p0 + 4];
        }
#pragma unroll
        for (int j = 0; j < 8; j++) {
            int widx = ((ncol0 + j) * 8 + s) * 32 + lane;   // uint2 index
            uint2 bh = __ldg((const uint2*)Wfh + widx);
            uint2 bl = __ldg((const uint2*)Wfl + widx);
#pragma unroll
            for (int mt = 0; mt < MT; mt++) {
                mma_bf16(acc[mt][j], ah[mt], bh.x, bh.y);
                mma_bf16(acc[mt][j], ah[mt], bl.x, bl.y);
            }
        }
    }

    // ---- epilogue: fragment -> bf16x2 packed H ----
#pragma unroll
    for (int mt = 0; mt < MT; mt++) {
#pragma unroll
        for (int j = 0; j < 8; j++) {
            int row = base + (wm + mt) * 16 + g;
            int col = (ncol0 + j) * 8 + tg * 2;      // even column
            if (row < n)
                H[(size_t)row * (NOUT / 2) + col / 2] = pack_bf16x2(acc[mt][j][0], acc[mt][j][1]);
            if (row + 8 < n)
                H[(size_t)(row + 8) * (NOUT / 2) + col / 2] = pack_bf16x2(acc[mt][j][2], acc[mt][j][3]);
        }
    }
}

// ---------------- aggregation: warp-per-node gather over sorted CSR --------
// H is bf16x2 packed. 2-edge software pipeline, single accumulator.
// 64-thread blocks (2 warps): fine-grained retirement minimizes tail-warp
// imbalance from the Poisson degree distribution.
template <int C, bool RELU, bool POOL>
__global__ __launch_bounds__(64) void k_agg(const uint32_t* __restrict__ H,
                                            const float* __restrict__ bias,
                                            uint32_t* __restrict__ Xo,
                                            const int* __restrict__ batch,
                                            int n) {
    int w = (blockIdx.x * blockDim.x + threadIdx.x) >> 5;
    int lane = threadIdx.x & 31;
    if (w >= n) return;
    int beg = g_rowoff[w];
    int end = g_rowoff[w + 1];

    if (C == 128) {
        float4 acc = make_float4(0.f, 0.f, 0.f, 0.f);
        const uint2* H2 = (const uint2*)H;   // 32 uint2 per row
        int j = beg;
        for (; j + 1 < end; j += 2) {
            int2 e0 = __ldg(&g_edge[j]);
            int2 e1 = __ldg(&g_edge[j + 1]);
            uint2 v0 = H2[(size_t)e0.x * 32 + lane];
            uint2 v1 = H2[(size_t)e1.x * 32 + lane];
            float wt0 = __int_as_float(e0.y);
            float wt1 = __int_as_float(e1.y);
            float2 a0 = __bfloat1622float2(*reinterpret_cast<__nv_bfloat162*>(&v0.x));
            float2 a1 = __bfloat1622float2(*reinterpret_cast<__nv_bfloat162*>(&v0.y));
            float2 b0 = __bfloat1622float2(*reinterpret_cast<__nv_bfloat162*>(&v1.x));
            float2 b1 = __bfloat1622float2(*reinterpret_cast<__nv_bfloat162*>(&v1.y));
            acc.x = fmaf(wt0, a0.x, acc.x);
            acc.y = fmaf(wt0, a0.y, acc.y);
            acc.z = fmaf(wt0, a1.x, acc.z);
            acc.w = fmaf(wt0, a1.y, acc.w);
            acc.x = fmaf(wt1, b0.x, acc.x);
            acc.y = fmaf(wt1, b0.y, acc.y);
            acc.z = fmaf(wt1, b1.x, acc.z);
            acc.w = fmaf(wt1, b1.y, acc.w);
        }
        if (j < end) {
            int2 e = __ldg(&g_edge[j]);
            float wt = __int_as_float(e.y);
            uint2 v = H2[(size_t)e.x * 32 + lane];
            float2 f0 = __bfloat1622float2(*reinterpret_cast<__nv_bfloat162*>(&v.x));
            float2 f1 = __bfloat1622float2(*reinterpret_cast<__nv_bfloat162*>(&v.y));
            acc.x = fmaf(wt, f0.x, acc.x);
            acc.y = fmaf(wt, f0.y, acc.y);
            acc.z = fmaf(wt, f1.x, acc.z);
            acc.w = fmaf(wt, f1.y, acc.w);
        }
        float di = g_dinv[w];
        float sl = di * di;
        uint2 v = H2[(size_t)w * 32 + lane];
        float2 h0 = __bfloat1622float2(*reinterpret_cast<__nv_bfloat162*>(&v.x));
        float2 h1 = __bfloat1622float2(*reinterpret_cast<__nv_bfloat162*>(&v.y));
        float4 bb = *(const float4*)&bias[lane * 4];
        acc.x = fmaf(sl, h0.x, acc.x) + bb.x;
        acc.y = fmaf(sl, h0.y, acc.y) + bb.y;
        acc.z = fmaf(sl, h1.x, acc.z) + bb.z;
        acc.w = fmaf(sl, h1.y, acc.w) + bb.w;
        if (RELU) {
            acc.x = fmaxf(acc.x, 0.f); acc.y = fmaxf(acc.y, 0.f);
            acc.z = fmaxf(acc.z, 0.f); acc.w = fmaxf(acc.w, 0.f);
        }
        // write as bf16x2 packed, streaming (consumed once by next GEMM)
        uint2 o;
        o.x = pack_bf16x2(acc.x, acc.y);
        o.y = pack_bf16x2(acc.z, acc.w);
        __stcs((uint2*)&Xo[(size_t)w * 64 + lane * 2], o);
    } else {  // C == 64
        float2 acc = make_float2(0.f, 0.f);
        int j = beg;
        for (; j + 1 < end; j += 2) {
            int2 e0 = __ldg(&g_edge[j]);
            int2 e1 = __ldg(&g_edge[j + 1]);
            uint32_t v0 = H[(size_t)e0.x * 32 + lane];
            uint32_t v1 = H[(size_t)e1.x * 32 + lane];
            float wt0 = __int_as_float(e0.y);
            float wt1 = __int_as_float(e1.y);
            float2 f0 = __bfloat1622float2(*reinterpret_cast<__nv_bfloat162*>(&v0));
            float2 f1 = __bfloat1622float2(*reinterpret_cast<__nv_bfloat162*>(&v1));
            acc.x = fmaf(wt0, f0.x, acc.x);
            acc.y = fmaf(wt0, f0.y, acc.y);
            acc.x = fmaf(wt1, f1.x, acc.x);
            acc.y = fmaf(wt1, f1.y, acc.y);
        }
        if (j < end) {
            int2 e = __ldg(&g_edge[j]);
            float wt = __int_as_float(e.y);
            uint32_t v = H[(size_t)e.x * 32 + lane];
            float2 f = __bfloat1622float2(*reinterpret_cast<__nv_bfloat162*>(&v));
            acc.x = fmaf(wt, f.x, acc.x);
            acc.y = fmaf(wt, f.y, acc.y);
        }
        float di = g_dinv[w];
        float sl = di * di;
        uint32_t v = H[(size_t)w * 32 + lane];
        float2 hd = __bfloat1622float2(*reinterpret_cast<__nv_bfloat162*>(&v));
        float2 bb = *(const float2*)&bias[lane * 2];
        acc.x = fmaf(sl, hd.x, acc.x) + bb.x;
        acc.y = fmaf(sl, hd.y, acc.y) + bb.y;
        if (RELU) { acc.x = fmaxf(acc.x, 0.f); acc.y = fmaxf(acc.y, 0.f); }
        if (POOL) {
            int b = batch[w];
            atomicAdd(&g_pool[b * C_OUT + lane * 2 + 0], acc.x);
            atomicAdd(&g_pool[b * C_OUT + lane * 2 + 1], acc.y);
            if (lane == 0) atomicAdd(&g_gcnt[b], 1.0f);
        }
    }
}

// ---------------- final FC on pooled means ----------------------------------
__global__ void k_fc(const float* __restrict__ Wfc, const float* __restrict__ bfc,
                     float* __restrict__ out) {
    int t = threadIdx.x;  // 128 = 64 graphs * 2 classes
    int g = t >> 1, c = t & 1;
    float s = 0.f;
#pragma unroll
    for (int k = 0; k < C_OUT; k++) s = fmaf(g_pool[g * C_OUT + k], Wfc[k * N_CLS + c], s);
    out[g * N_CLS + c] = s / fmaxf(g_gcnt[g], 1.0f) + bfc[c];
}

// ---------------- launch ----------------------------------------------------
extern "C" void kernel_launch(void* const* d_in, const int* in_sizes, int n_in,
                              void* d_out, int out_size) {
    const float* x    = (const float*)d_in[0];
    const int*   ei   = (const int*)d_in[1];
    const int*   batch= (const int*)d_in[2];
    const float* W1   = (const float*)d_in[3];
    const float* b1   = (const float*)d_in[4];
    const float* W2   = (const float*)d_in[5];
    const float* b2   = (const float*)d_in[6];
    const float* W3   = (const float*)d_in[7];
    const float* b3   = (const float*)d_in[8];
    const float* Wfc  = (const float*)d_in[9];
    const float* bfc  = (const float*)d_in[10];
    float* out = (float*)d_out;

    const int* src = ei;
    const int* dst = ei + NE;

    void *pH, *pX, *p1h, *p1l, *p2h, *p2l, *p3h, *p3l;
    cudaGetSymbolAddress(&pH, g_H);
    cudaGetSymbolAddress(&pX, g_X);
    cudaGetSymbolAddress(&p1h, g_W1h);
    cudaGetSymbolAddress(&p1l, g_W1l);
    cudaGetSymbolAddress(&p2h, g_W2h);
    cudaGetSymbolAddress(&p2l, g_W2l);
    cudaGetSymbolAddress(&p3h, g_W3h);
    cudaGetSymbolAddress(&p3l, g_W3l);
    uint32_t* H = (uint32_t*)pH;
    uint32_t* X = (uint32_t*)pX;

    const int SMEM = XWORDS * 4;   // 34816 B (Xh tile only)
    cudaFuncSetAttribute((void*)k_mmagemm<128, false>, cudaFuncAttributeMaxDynamicSharedMemorySize, SMEM);
    cudaFuncSetAttribute((void*)k_mmagemm<128, true>,  cudaFuncAttributeMaxDynamicSharedMemorySize, SMEM);
    cudaFuncSetAttribute((void*)k_mmagemm<64, true>,   cudaFuncAttributeMaxDynamicSharedMemorySize, SMEM);

    const int NB = (NN + 1023) / 1024;  // 98 scan blocks
    const int gemm_grid = (NN + 127) / 128;  // 782
    const int agg_grid  = (NN + 1) / 2;      // 2 warps/block, warp per node

    // preprocessing + layer-1 GEMM
    k_pre<<<(NN + 255) / 256, 256>>>(W1, W2, W3);     // zero + W pack (fused)
    k_hist<<<(NE / 4 + 255) / 256, 256>>>((const int4*)dst);
    k_mmagemm<128, false><<<gemm_grid, 256, SMEM>>>(x, (const uint32_t*)p1h,
                                                    (const uint32_t*)p1l, H, NN);
    k_scan1<<<NB, 256>>>();
    k_scan2<<<1, 128>>>(NB);
    k_scan3<<<(NN + 255) / 256, 256>>>();   // fused: fixup + cursor + dinv
    k_esort<<<(NE + 255) / 256, 256>>>(src, dst);

    // layer 1 agg
    k_agg<128, true, false><<<agg_grid, 64>>>(H, b1, X, nullptr, NN);
    // layer 2
    k_mmagemm<128, true><<<gemm_grid, 256, SMEM>>>(X, (const uint32_t*)p2h,
                                                   (const uint32_t*)p2l, H, NN);
    k_agg<128, true, false><<<agg_grid, 64>>>(H, b2, X, nullptr, NN);
    // layer 3 (C=64), pooling fused
    k_mmagemm<64, true><<<gemm_grid, 256, SMEM>>>(X, (const uint32_t*)p3h,
                                                  (const uint32_t*)p3l, H, NN);
    k_agg<64, false, true><<<agg_grid, 64>>>(H, b3, nullptr, batch, NN);
    // FC head
    k_fc<<<1, 128>>>(Wfc, bfc, out);
}